// round 16
// baseline (speedup 1.0000x reference)
#include <cuda_runtime.h>

#define WARPS_PER_BLOCK 8
#define THREADS_PER_BLOCK (WARPS_PER_BLOCK * 32)
#define BLOCKS_PER_SM 8
#define CHUNK 8   // empirically optimal grain (R9)

// Vectorized zero-out: out_size=20000 -> 5000 float4 stores.
__global__ void zero_out_kernel(float4* out4, int n4) {
    int i = blockIdx.x * blockDim.x + threadIdx.x;
    if (i < n4) out4[i] = make_float4(0.f, 0.f, 0.f, 0.f);
}

// Warp-reduce per-lane accumulator and atomically flush to out[seg_id].
__device__ __forceinline__ void flush_seg(float& acc, int seg_id, int lane,
                                          float* __restrict__ out) {
    float s = acc;
    #pragma unroll
    for (int off = 16; off > 0; off >>= 1)
        s += __shfl_xor_sync(0xFFFFFFFFu, s, off);
    if (lane == 0) atomicAdd(&out[seg_id], s);
    acc = 0.0f;
}

__launch_bounds__(THREADS_PER_BLOCK, BLOCKS_PER_SM)
__global__ void atomwise_readout_kernel(const float4* __restrict__ f4,
                                        const int* __restrict__ seg,
                                        const float* __restrict__ w,
                                        float* __restrict__ out,
                                        int n_atoms) {
    const int lane = threadIdx.x & 31;
    const int warp_global = blockIdx.x * WARPS_PER_BLOCK + (threadIdx.x >> 5);

    // All-int32 indexing: max atom index 2M, max float4 index 64M — fits.
    int start = warp_global * CHUNK;
    if (start >= n_atoms) return;
    int end = start + CHUNK;
    if (end > n_atoms) end = n_atoms;

    const float4 wv = reinterpret_cast<const float4*>(w)[lane];  // L1/L2 hit

    int   cur_seg = seg[start];
    float acc     = 0.0f;     // per-LANE partial sum for current segment run

    int a = start;
    const float4* p = f4 + (unsigned)start * 32u + (unsigned)lane;

    // Main loop: 4 atoms/iter. 5 loads batched at the top; sorted seg ids ->
    // per-lane accumulation, warp-reduce only on segment change.
    for (; a + 4 <= end; a += 4, p += 128) {
        int4 g = *reinterpret_cast<const int4*>(&seg[a]);

        float4 v0 = __ldcs(p);
        float4 v1 = __ldcs(p + 32);
        float4 v2 = __ldcs(p + 64);
        float4 v3 = __ldcs(p + 96);

        float s0 = fmaf(v0.x, wv.x, fmaf(v0.y, wv.y, fmaf(v0.z, wv.z, v0.w * wv.w)));
        float s1 = fmaf(v1.x, wv.x, fmaf(v1.y, wv.y, fmaf(v1.z, wv.z, v1.w * wv.w)));
        float s2 = fmaf(v2.x, wv.x, fmaf(v2.y, wv.y, fmaf(v2.z, wv.z, v2.w * wv.w)));
        float s3 = fmaf(v3.x, wv.x, fmaf(v3.y, wv.y, fmaf(v3.z, wv.z, v3.w * wv.w)));

        if (g.w == cur_seg) {
            acc += (s0 + s1) + (s2 + s3);   // fast path: quad in one segment
        } else {
            if (g.x != cur_seg) { flush_seg(acc, cur_seg, lane, out); cur_seg = g.x; }
            acc += s0;
            if (g.y != cur_seg) { flush_seg(acc, cur_seg, lane, out); cur_seg = g.y; }
            acc += s1;
            if (g.z != cur_seg) { flush_seg(acc, cur_seg, lane, out); cur_seg = g.z; }
            acc += s2;
            if (g.w != cur_seg) { flush_seg(acc, cur_seg, lane, out); cur_seg = g.w; }
            acc += s3;
        }
    }

    // Tail (< 4 atoms, only at the very end of the array)
    for (; a < end; a++, p += 32) {
        float4 v = __ldcs(p);
        float s = fmaf(v.x, wv.x, fmaf(v.y, wv.y, fmaf(v.z, wv.z, v.w * wv.w)));
        int gg = seg[a];
        if (gg != cur_seg) { flush_seg(acc, cur_seg, lane, out); cur_seg = gg; }
        acc += s;
    }

    flush_seg(acc, cur_seg, lane, out);
}

extern "C" void kernel_launch(void* const* d_in, const int* in_sizes, int n_in,
                              void* d_out, int out_size) {
    const float* f   = (const float*)d_in[0];
    const int*   seg = (const int*)d_in[1];
    const float* w   = (const float*)d_in[n_in - 1];  // w_e (128 floats) is last

    const int n_atoms = in_sizes[1];
    float* out = (float*)d_out;

    // Zero the poisoned output (out_size = 20000, divisible by 4).
    {
        int n4      = out_size >> 2;
        int threads = 128;
        int blocks  = (n4 + threads - 1) / threads;
        zero_out_kernel<<<blocks, threads>>>(reinterpret_cast<float4*>(out), n4);
    }

    // Exact cover: every warp (except possibly the last) gets exactly CHUNK atoms.
    const int total_warps = (n_atoms + CHUNK - 1) / CHUNK;
    const int blocks = (total_warps + WARPS_PER_BLOCK - 1) / WARPS_PER_BLOCK;

    atomwise_readout_kernel<<<blocks, THREADS_PER_BLOCK>>>(
        reinterpret_cast<const float4*>(f), seg, w, out, n_atoms);
}

// round 17
// speedup vs baseline: 1.0160x; 1.0160x over previous
#include <cuda_runtime.h>

#define WARPS_PER_BLOCK 8
#define THREADS_PER_BLOCK (WARPS_PER_BLOCK * 32)
#define BLOCKS_PER_SM 8
#define CHUNK 8   // atoms per warp (multiple of 4); grid sized to cover exactly

__global__ void zero_out_kernel(float* out, int n) {
    int i = blockIdx.x * blockDim.x + threadIdx.x;
    if (i < n) out[i] = 0.0f;
}

// Warp-reduce per-lane accumulator and atomically flush to out[seg_id].
__device__ __forceinline__ void flush_seg(float& acc, int seg_id, int lane,
                                          float* __restrict__ out) {
    float s = acc;
    #pragma unroll
    for (int off = 16; off > 0; off >>= 1)
        s += __shfl_xor_sync(0xFFFFFFFFu, s, off);
    if (lane == 0) atomicAdd(&out[seg_id], s);
    acc = 0.0f;
}

__launch_bounds__(THREADS_PER_BLOCK, BLOCKS_PER_SM)
__global__ void atomwise_readout_kernel(const float4* __restrict__ f4,
                                        const int* __restrict__ seg,
                                        const float* __restrict__ w,
                                        float* __restrict__ out,
                                        int n_atoms) {
    const int lane = threadIdx.x & 31;
    const int warp_global = blockIdx.x * WARPS_PER_BLOCK + (threadIdx.x >> 5);

    long long start = (long long)warp_global * CHUNK;
    if (start >= n_atoms) return;
    long long end = start + CHUNK;
    if (end > n_atoms) end = n_atoms;

    const float4 wv = reinterpret_cast<const float4*>(w)[lane];  // L1/L2 hit

    int   cur_seg = seg[start];
    float acc     = 0.0f;     // per-LANE partial sum for current segment run

    long long a = start;
    const float4* p = f4 + start * 32 + lane;

    // Main loop: 4 atoms/iter. 5 loads batched at the top; sorted seg ids ->
    // per-lane accumulation, warp-reduce only on segment change.
    for (; a + 4 <= end; a += 4, p += 128) {
        int4 g = *reinterpret_cast<const int4*>(&seg[a]);

        float4 v0 = __ldcs(p);
        float4 v1 = __ldcs(p + 32);
        float4 v2 = __ldcs(p + 64);
        float4 v3 = __ldcs(p + 96);

        float s0 = fmaf(v0.x, wv.x, fmaf(v0.y, wv.y, fmaf(v0.z, wv.z, v0.w * wv.w)));
        float s1 = fmaf(v1.x, wv.x, fmaf(v1.y, wv.y, fmaf(v1.z, wv.z, v1.w * wv.w)));
        float s2 = fmaf(v2.x, wv.x, fmaf(v2.y, wv.y, fmaf(v2.z, wv.z, v2.w * wv.w)));
        float s3 = fmaf(v3.x, wv.x, fmaf(v3.y, wv.y, fmaf(v3.z, wv.z, v3.w * wv.w)));

        if (g.w == cur_seg) {
            acc += (s0 + s1) + (s2 + s3);   // fast path: quad in one segment
        } else {
            if (g.x != cur_seg) { flush_seg(acc, cur_seg, lane, out); cur_seg = g.x; }
            acc += s0;
            if (g.y != cur_seg) { flush_seg(acc, cur_seg, lane, out); cur_seg = g.y; }
            acc += s1;
            if (g.z != cur_seg) { flush_seg(acc, cur_seg, lane, out); cur_seg = g.z; }
            acc += s2;
            if (g.w != cur_seg) { flush_seg(acc, cur_seg, lane, out); cur_seg = g.w; }
            acc += s3;
        }
    }

    // Tail (< 4 atoms, only at the very end of the array)
    for (; a < end; a++, p += 32) {
        float4 v = __ldcs(p);
        float s = fmaf(v.x, wv.x, fmaf(v.y, wv.y, fmaf(v.z, wv.z, v.w * wv.w)));
        int gg = seg[a];
        if (gg != cur_seg) { flush_seg(acc, cur_seg, lane, out); cur_seg = gg; }
        acc += s;
    }

    flush_seg(acc, cur_seg, lane, out);
}

extern "C" void kernel_launch(void* const* d_in, const int* in_sizes, int n_in,
                              void* d_out, int out_size) {
    const float* f   = (const float*)d_in[0];
    const int*   seg = (const int*)d_in[1];
    const float* w   = (const float*)d_in[n_in - 1];  // w_e (128 floats) is last

    const int n_atoms = in_sizes[1];
    float* out = (float*)d_out;

    {
        int threads = 128;
        int blocks  = (out_size + threads - 1) / threads;
        zero_out_kernel<<<blocks, threads>>>(out, out_size);
    }

    // Exact cover: every warp (except possibly the last) gets exactly CHUNK atoms.
    const long long total_warps = ((long long)n_atoms + CHUNK - 1) / CHUNK;
    const int blocks = (int)((total_warps + WARPS_PER_BLOCK - 1) / WARPS_PER_BLOCK);

    atomwise_readout_kernel<<<blocks, THREADS_PER_BLOCK>>>(
        reinterpret_cast<const float4*>(f), seg, w, out, n_atoms);
}